// round 4
// baseline (speedup 1.0000x reference)
#include <cuda_runtime.h>
#include <math.h>
#include <stdint.h>

#define NMAX 100000
#define EMAX 1600000
#define F 128
#define HEADC 106   // 64 + 40 + 1 + 1
#define HEADP 108
#define SCHUNK 512

// ---------------- scratch (static device globals; no allocation allowed) ---
__device__ float g_h[(size_t)NMAX * F];       // GEMM output / gather source
__device__ float g_agg[(size_t)NMAX * F];     // aggregation output
__device__ float g_dinv[NMAX];
__device__ int   g_deg[NMAX];
__device__ int   g_rowptr[NMAX + 1];
__device__ int   g_fill[NMAX];
__device__ int   g_row[EMAX];
__device__ int   g_col[EMAX];
__device__ int   g_src[EMAX];                 // CSR (by destination) source ids
__device__ int   g_bsum[256];
__device__ float g_hw[F * HEADP];
__device__ float g_hb[HEADP];
__device__ int   g_is64;

// ---------------- detect dtype + zero degrees (fused) ----------------------
__global__ void zdetect_kernel(const int* __restrict__ e, int n) {
    int i = blockIdx.x * blockDim.x + threadIdx.x;
    if (i < n) g_deg[i] = 0;
    if (blockIdx.x == 0 && threadIdx.x < 32) {
        int l = threadIdx.x;
        int bad = 0;
        for (int j = l; j < 256; j += 32)
            if (e[2 * j + 1] != 0) bad = 1;
        unsigned b = __ballot_sync(0xffffffffu, bad);
        if (l == 0) g_is64 = (b == 0) ? 1 : 0;
    }
}

__device__ __forceinline__ int ldidx(const void* p, long long i, int is64) {
    return is64 ? (int)((const long long*)p)[i] : ((const int*)p)[i];
}

// ---------------- convert indices to int32 + count degrees (fused) ----------
__global__ void convcount_kernel(const void* __restrict__ eidx, long long E) {
    long long t = (long long)blockIdx.x * blockDim.x + threadIdx.x;
    if (t >= E) return;
    int is64 = g_is64;
    int r = ldidx(eidx, t, is64);
    int c = ldidx(eidx, E + t, is64);
    g_row[t] = r;
    g_col[t] = c;
    atomicAdd(&g_deg[c], 1);
}

// ---------------- hierarchical scan (2 stages) ------------------------------
__global__ void scan1_kernel(int n) {
    __shared__ int sh[SCHUNK];
    int t = threadIdx.x;
    int i = blockIdx.x * SCHUNK + t;
    sh[t] = (i < n) ? g_deg[i] : 0;
    __syncthreads();
#pragma unroll
    for (int off = SCHUNK / 2; off; off >>= 1) {
        if (t < off) sh[t] += sh[t + off];
        __syncthreads();
    }
    if (t == 0) g_bsum[blockIdx.x] = sh[0];
}

// merged: every block scans the 196 block sums locally, then scans its chunk
__global__ void scan3_kernel(int n, int nb) {
    __shared__ int bs[256];
    __shared__ int sh[SCHUNK];
    int t = threadIdx.x;
    if (t < 256) bs[t] = (t < nb) ? g_bsum[t] : 0;
    __syncthreads();
#pragma unroll
    for (int off = 1; off < 256; off <<= 1) {
        int u = (t < 256 && t >= off) ? bs[t - off] : 0;
        __syncthreads();
        if (t < 256) bs[t] += u;
        __syncthreads();
    }
    int boff = (blockIdx.x == 0) ? 0 : bs[blockIdx.x - 1];
    if (blockIdx.x == 0 && t == 0) g_rowptr[n] = bs[nb - 1];

    int i = blockIdx.x * SCHUNK + t;
    int d = (i < n) ? g_deg[i] : 0;
    sh[t] = d;
    __syncthreads();
#pragma unroll
    for (int off = 1; off < SCHUNK; off <<= 1) {
        int u = (t >= off) ? sh[t - off] : 0;
        __syncthreads();
        sh[t] += u;
        __syncthreads();
    }
    if (i < n) {
        int pre = boff + sh[t] - d;
        g_rowptr[i] = pre;
        g_fill[i]   = pre;
        g_dinv[i]   = rsqrtf((float)(d + 1));  // +1 self-loop
    }
}

__global__ void fill_kernel(long long E) {
    long long e = (long long)blockIdx.x * blockDim.x + threadIdx.x;
    if (e >= E) return;
    int c = g_col[e];
    int pos = atomicAdd(&g_fill[c], 1);
    g_src[pos] = g_row[e];
}

// ---------------- packed-f32x2 SGEMM: C[M,128] = A[M,128] @ W[128,128] ------
// 128x128 block tile, 8x8 per-thread register tile, fma.rn.f32x2 (FFMA2).
__device__ __forceinline__ unsigned long long pack2(float v) {
    unsigned long long r;
    unsigned u = __float_as_uint(v);
    asm("mov.b64 %0, {%1, %1};" : "=l"(r) : "r"(u));
    return r;
}
__device__ __forceinline__ void ffma2(unsigned long long& acc,
                                      unsigned long long a,
                                      unsigned long long b) {
    asm("fma.rn.f32x2 %0, %1, %2, %0;" : "+l"(acc) : "l"(a), "l"(b));
}

__global__ __launch_bounds__(256)
void gemm_kernel(const float* __restrict__ A, const float* __restrict__ W,
                 float* __restrict__ C, int M) {
    extern __shared__ float sm[];
    float* Ws = sm;            // [128][128]
    float* xs = Ws + F * F;    // [128 rows][32 float4 chunks], xor-swizzled

    int tid = threadIdx.x;
    // stage W
    for (int i = tid; i < F * 32; i += 256)
        ((float4*)Ws)[i] = ((const float4*)W)[i];
    // stage x rows with per-8-row xor swizzle on the float4 chunk index
    long long row0 = (long long)blockIdx.x * 128;
    float4* xs4 = (float4*)xs;
    for (int i = tid; i < F * 32; i += 256) {
        int r = i >> 5, cq = i & 31;
        long long gr = row0 + r;
        float4 v = make_float4(0.f, 0.f, 0.f, 0.f);
        if (gr < M) v = ((const float4*)(A + gr * F))[cq];
        xs4[r * 32 + (cq ^ ((r >> 3) & 1))] = v;
    }
    __syncthreads();

    int w = tid >> 5, lane = tid & 31;
    int lr = lane >> 4, lc = lane & 15;
    int rbase = w * 16 + lr * 8;           // 8 rows for this thread
    int c0 = lc * 4, c1 = 64 + lc * 4;     // two distant col quads
    int swz = lr;                          // xor bit for x chunk index

    unsigned long long acc[8][4];
#pragma unroll
    for (int r = 0; r < 8; r++)
#pragma unroll
        for (int m = 0; m < 4; m++) acc[r][m] = 0ull;

    for (int k = 0; k < F; k += 4) {
        ulonglong2 wa[4], wb[4];
#pragma unroll
        for (int kk = 0; kk < 4; kk++) {
            wa[kk] = *(const ulonglong2*)&Ws[(k + kk) * F + c0];
            wb[kk] = *(const ulonglong2*)&Ws[(k + kk) * F + c1];
        }
        float4 xv[8];
        int kq = k >> 2;
#pragma unroll
        for (int r = 0; r < 8; r++)
            xv[r] = xs4[(rbase + r) * 32 + (kq ^ swz)];
#pragma unroll
        for (int kk = 0; kk < 4; kk++) {
#pragma unroll
            for (int r = 0; r < 8; r++) {
                float xf = (kk == 0) ? xv[r].x : (kk == 1) ? xv[r].y
                         : (kk == 2) ? xv[r].z : xv[r].w;
                unsigned long long xx = pack2(xf);
                ffma2(acc[r][0], xx, wa[kk].x);
                ffma2(acc[r][1], xx, wa[kk].y);
                ffma2(acc[r][2], xx, wb[kk].x);
                ffma2(acc[r][3], xx, wb[kk].y);
            }
        }
    }

#pragma unroll
    for (int r = 0; r < 8; r++) {
        long long gr = row0 + rbase + r;
        if (gr >= M) break;
        float4 o;
        o.x = __uint_as_float((unsigned)(acc[r][0] & 0xffffffffull));
        o.y = __uint_as_float((unsigned)(acc[r][0] >> 32));
        o.z = __uint_as_float((unsigned)(acc[r][1] & 0xffffffffull));
        o.w = __uint_as_float((unsigned)(acc[r][1] >> 32));
        *(float4*)(C + gr * F + c0) = o;
        o.x = __uint_as_float((unsigned)(acc[r][2] & 0xffffffffull));
        o.y = __uint_as_float((unsigned)(acc[r][2] >> 32));
        o.z = __uint_as_float((unsigned)(acc[r][3] & 0xffffffffull));
        o.w = __uint_as_float((unsigned)(acc[r][3] >> 32));
        *(float4*)(C + gr * F + c1) = o;
    }
}

// ---------------- CSR gather aggregation (no atomics), fused epilogue ------
// mode 1: +b1, BN(eval), ReLU.   mode 2: +b2.
__global__ void agg_kernel(int n, int mode,
                           const float* __restrict__ bias,
                           const float* __restrict__ gamma,
                           const float* __restrict__ beta,
                           const float* __restrict__ mean,
                           const float* __restrict__ var) {
    int node = blockIdx.x * (blockDim.x >> 5) + (threadIdx.x >> 5);
    if (node >= n) return;
    int l = threadIdx.x & 31;

    float d = g_dinv[node];
    const float4* hv = (const float4*)g_h;

    float4 acc = hv[(size_t)node * 32 + l];
    float d2 = d * d;
    acc.x *= d2; acc.y *= d2; acc.z *= d2; acc.w *= d2;
    float4 acc2 = make_float4(0.f, 0.f, 0.f, 0.f);

    int s = g_rowptr[node], e2 = g_rowptr[node + 1];
    for (int base = s; base < e2; base += 32) {
        int idx = base + l;
        int r = (idx < e2) ? g_src[idx] : 0;
        float dr = (idx < e2) ? g_dinv[r] : 0.f;
        int m = e2 - base; if (m > 32) m = 32;
        int j = 0;
        for (; j + 2 <= m; j += 2) {
            int r0 = __shfl_sync(0xffffffffu, r, j);
            int r1 = __shfl_sync(0xffffffffu, r, j + 1);
            float n0 = __shfl_sync(0xffffffffu, dr, j) * d;
            float n1 = __shfl_sync(0xffffffffu, dr, j + 1) * d;
            float4 v0 = __ldg(hv + (size_t)r0 * 32 + l);
            float4 v1 = __ldg(hv + (size_t)r1 * 32 + l);
            acc.x += v0.x * n0; acc.y += v0.y * n0;
            acc.z += v0.z * n0; acc.w += v0.w * n0;
            acc2.x += v1.x * n1; acc2.y += v1.y * n1;
            acc2.z += v1.z * n1; acc2.w += v1.w * n1;
        }
        if (j < m) {
            int r0 = __shfl_sync(0xffffffffu, r, j);
            float n0 = __shfl_sync(0xffffffffu, dr, j) * d;
            float4 v0 = __ldg(hv + (size_t)r0 * 32 + l);
            acc.x += v0.x * n0; acc.y += v0.y * n0;
            acc.z += v0.z * n0; acc.w += v0.w * n0;
        }
    }
    acc.x += acc2.x; acc.y += acc2.y; acc.z += acc2.z; acc.w += acc2.w;

    int c0 = 4 * l;
    float out[4] = {acc.x, acc.y, acc.z, acc.w};
    if (mode == 1) {
#pragma unroll
        for (int m = 0; m < 4; m++) {
            int c = c0 + m;
            float v = out[m] + bias[c];
            float sc = gamma[c] * rsqrtf(var[c] + 1e-5f);
            v = (v - mean[c]) * sc + beta[c];
            out[m] = fmaxf(v, 0.f);
        }
    } else {
#pragma unroll
        for (int m = 0; m < 4; m++) out[m] += bias[c0 + m];
    }
    *(float4*)(g_agg + (size_t)node * F + c0) =
        make_float4(out[0], out[1], out[2], out[3]);
}

// ---------------- head weight packing ---------------------------------------
__global__ void pack_heads_kernel(const float* __restrict__ cls_w,
                                  const float* __restrict__ cls_b,
                                  const float* __restrict__ sim_w,
                                  const float* __restrict__ sim_b,
                                  const float* __restrict__ hom_w,
                                  const float* __restrict__ hom_b,
                                  const float* __restrict__ ent_w,
                                  const float* __restrict__ ent_b) {
    int t = blockIdx.x * blockDim.x + threadIdx.x;
    if (t < F * HEADP) {
        int k = t / HEADP, c = t % HEADP;
        float v = 0.f;
        if (c < 64)        v = cls_w[k * 64 + c];
        else if (c < 104)  v = sim_w[k * 40 + (c - 64)];
        else if (c == 104) v = hom_w[k];
        else if (c == 105) v = ent_w[k];
        g_hw[t] = v;
    }
    if (t < HEADP) {
        float v = 0.f;
        if (t < 64)        v = cls_b[t];
        else if (t < 104)  v = sim_b[t - 64];
        else if (t == 104) v = hom_b[0];
        else if (t == 105) v = ent_b[0];
        g_hb[t] = v;
    }
}

// ---------------- head GEMM [M,128]x[128,106] with fused finisher -----------
__global__ void head_kernel(const float* __restrict__ A,
                            float* __restrict__ out, int M) {
    extern __shared__ float sm[];
    float* Ws = sm;                    // F * HEADP
    float* xs = Ws + F * HEADP;        // 8 * 4 * F
    float* sb = xs + 8 * 4 * F;        // HEADP

    int tid = threadIdx.x;
    for (int i = tid; i < F * HEADP; i += blockDim.x) Ws[i] = g_hw[i];
    for (int c = tid; c < HEADP; c += blockDim.x) sb[c] = g_hb[c];
    __syncthreads();

    int wid = tid >> 5, l = tid & 31;
    long long row0 = ((long long)blockIdx.x * 8 + wid) * 4;
    if (row0 >= M) return;

    float* xw = xs + wid * 4 * F;
#pragma unroll
    for (int rr = 0; rr < 4; rr++) {
        long long r = row0 + rr;
        float4 v = make_float4(0.f, 0.f, 0.f, 0.f);
        if (r < M) v = __ldg((const float4*)(A + r * F) + l);
        *(float4*)&xw[rr * F + 4 * l] = v;
    }
    __syncwarp();

    float acc[4][4];
#pragma unroll
    for (int rr = 0; rr < 4; rr++)
#pragma unroll
        for (int m = 0; m < 4; m++) acc[rr][m] = 0.f;

    const float4* WsV = (const float4*)Ws;
    const int ncp4 = HEADP >> 2;  // 27
#pragma unroll
    for (int k = 0; k < F; k += 4) {
        float4 w4[4], xr[4];
#pragma unroll
        for (int kk = 0; kk < 4; kk++)
            w4[kk] = (l < ncp4) ? WsV[(k + kk) * ncp4 + l]
                                : make_float4(0.f, 0.f, 0.f, 0.f);
#pragma unroll
        for (int rr = 0; rr < 4; rr++) xr[rr] = *(const float4*)&xw[rr * F + k];
#pragma unroll
        for (int rr = 0; rr < 4; rr++) {
            const float* xf = (const float*)&xr[rr];
#pragma unroll
            for (int kk = 0; kk < 4; kk++) {
                const float* wf = (const float*)&w4[kk];
                float xv = xf[kk];
                acc[rr][0] += xv * wf[0];
                acc[rr][1] += xv * wf[1];
                acc[rr][2] += xv * wf[2];
                acc[rr][3] += xv * wf[3];
            }
        }
    }

    float* out_main = out;                     // [M,64]
    float* out_sim  = out + (size_t)M * 64;    // [M,40]
    float* out_hom  = out + (size_t)M * 104;   // [M]
    float* out_ent  = out + (size_t)M * 105;   // [M]

    int c0 = 4 * l;
#pragma unroll
    for (int rr = 0; rr < 4; rr++) {
        long long r = row0 + rr;
        if (r >= M) break;
        float v[4];
#pragma unroll
        for (int m = 0; m < 4; m++)
            v[m] = acc[rr][m] + ((l < ncp4) ? sb[c0 + m] : 0.f);

        // log_softmax over cols [0,64) -> lanes 0..15
        float lm = -3.0e38f;
        if (l < 16) {
#pragma unroll
            for (int m = 0; m < 4; m++) lm = fmaxf(lm, v[m]);
        }
#pragma unroll
        for (int o = 16; o; o >>= 1)
            lm = fmaxf(lm, __shfl_xor_sync(0xffffffffu, lm, o));
        float se = 0.f;
        if (l < 16) {
#pragma unroll
            for (int m = 0; m < 4; m++) se += expf(v[m] - lm);
        }
#pragma unroll
        for (int o = 16; o; o >>= 1) se += __shfl_xor_sync(0xffffffffu, se, o);
        float ls = lm + logf(se);
        if (l < 16) {
#pragma unroll
            for (int m = 0; m < 4; m++) out_main[r * 64 + c0 + m] = v[m] - ls;
        }

        // softmax over cols [64,104) -> lanes 16..25
        bool insim = (l >= 16 && l < 26);
        float lm2 = -3.0e38f;
        if (insim) {
#pragma unroll
            for (int m = 0; m < 4; m++) lm2 = fmaxf(lm2, v[m]);
        }
#pragma unroll
        for (int o = 16; o; o >>= 1)
            lm2 = fmaxf(lm2, __shfl_xor_sync(0xffffffffu, lm2, o));
        float e4[4];
        float se2 = 0.f;
        if (insim) {
#pragma unroll
            for (int m = 0; m < 4; m++) { e4[m] = expf(v[m] - lm2); se2 += e4[m]; }
        }
#pragma unroll
        for (int o = 16; o; o >>= 1) se2 += __shfl_xor_sync(0xffffffffu, se2, o);
        if (insim) {
            float inv = 1.f / se2;
#pragma unroll
            for (int m = 0; m < 4; m++)
                out_sim[r * 40 + (c0 - 64) + m] = e4[m] * inv;
        }

        // sigmoids: col 104, 105 -> lane 26
        if (l == 26) {
            out_hom[r] = 1.f / (1.f + expf(-v[0]));
            out_ent[r] = 1.f / (1.f + expf(-v[1]));
        }
    }
}

// ---------------- launch ------------------------------------------------------
extern "C" void kernel_launch(void* const* d_in, const int* in_sizes, int n_in,
                              void* d_out, int out_size) {
    const float* x     = (const float*)d_in[0];
    const void*  eidx  = d_in[1];
    const float* w1    = (const float*)d_in[2];
    const float* b1    = (const float*)d_in[3];
    const float* w2    = (const float*)d_in[4];
    const float* b2    = (const float*)d_in[5];
    const float* gamma = (const float*)d_in[6];
    const float* beta  = (const float*)d_in[7];
    const float* mean  = (const float*)d_in[8];
    const float* var   = (const float*)d_in[9];
    const float* cls_w = (const float*)d_in[10];
    const float* cls_b = (const float*)d_in[11];
    const float* sim_w = (const float*)d_in[12];
    const float* sim_b = (const float*)d_in[13];
    const float* hom_w = (const float*)d_in[14];
    const float* hom_b = (const float*)d_in[15];
    const float* ent_w = (const float*)d_in[16];
    const float* ent_b = (const float*)d_in[17];

    int N = in_sizes[0] / F;
    long long E = (long long)in_sizes[1] / 2;
    float* out = (float*)d_out;

    float *p_h = nullptr, *p_agg = nullptr;
    cudaGetSymbolAddress((void**)&p_h, g_h);
    cudaGetSymbolAddress((void**)&p_agg, g_agg);

    size_t smemG = (size_t)(F * F * 2) * sizeof(float);   // 128KB
    size_t smemH = (size_t)(F * HEADP + 8 * 4 * F + HEADP) * sizeof(float);
    cudaFuncSetAttribute(gemm_kernel, cudaFuncAttributeMaxDynamicSharedMemorySize,
                         (int)smemG);
    cudaFuncSetAttribute(head_kernel, cudaFuncAttributeMaxDynamicSharedMemorySize,
                         96 * 1024);

    int tb = 256;
    int nscan = (N + SCHUNK - 1) / SCHUNK;
    int gemmG = (N + 127) / 128;

    // preprocessing: (0) zero+detect, (1) convert+count, (2) scan1,
    //                (3) scan3 merged, (4) fill
    zdetect_kernel<<<(N + tb - 1) / tb, tb>>>((const int*)eidx, N);
    convcount_kernel<<<(unsigned)((E + tb - 1) / tb), tb>>>(eidx, E);
    scan1_kernel<<<nscan, SCHUNK>>>(N);
    scan3_kernel<<<nscan, SCHUNK>>>(N, nscan);
    fill_kernel<<<(unsigned)((E + tb - 1) / tb), tb>>>(E);

    // layer 1  (gemm1 is launch index 5 -> ncu profiles it)
    gemm_kernel<<<gemmG, tb, smemG>>>(x, w1, p_h, N);
    agg_kernel<<<(N + 7) / 8, tb>>>(N, 1, b1, gamma, beta, mean, var);

    // layer 2
    gemm_kernel<<<gemmG, tb, smemG>>>(p_agg, w2, p_h, N);
    agg_kernel<<<(N + 7) / 8, tb>>>(N, 2, b2, nullptr, nullptr, nullptr, nullptr);

    // heads (fused finisher)
    pack_heads_kernel<<<(F * HEADP + tb - 1) / tb, tb>>>(cls_w, cls_b, sim_w, sim_b,
                                                         hom_w, hom_b, ent_w, ent_b);
    head_kernel<<<(N + 31) / 32, tb, smemH>>>(p_agg, out, N);
}

// round 6
// speedup vs baseline: 1.2035x; 1.2035x over previous
#include <cuda_runtime.h>
#include <math.h>
#include <stdint.h>

#define NMAX 100000
#define EMAX 1600000
#define F 128
#define HEADC 106   // 64 + 40 + 1 + 1
#define HEADP 108
#define SCHUNK 512

// ---------------- scratch (static device globals; no allocation allowed) ---
__device__ float g_h[(size_t)NMAX * F];       // GEMM output / gather source
__device__ float g_agg[(size_t)NMAX * F];     // aggregation output
__device__ float g_dinv[NMAX];
__device__ int   g_deg[NMAX];
__device__ int   g_rowptr[NMAX + 1];
__device__ int   g_fill[NMAX];
__device__ int   g_row[EMAX];
__device__ int   g_col[EMAX];
__device__ int   g_src[EMAX];                 // CSR (by destination) source ids
__device__ int   g_bsum[256];
__device__ float g_hw[F * HEADP];
__device__ float g_hb[HEADP];
__device__ int   g_is64;
// W fragment image: [4 k-chunks][64 tiles][2 regs][32 lanes] of (hi,lo)
__device__ float2 g_bimg[16384];

__device__ __forceinline__ float tf32_rna(float x) {
    unsigned r;
    asm("cvt.rna.tf32.f32 %0, %1;" : "=r"(r) : "f"(x));
    return __uint_as_float(r);
}

#define MMA_TF32(cc, a, b)                                                     \
    asm volatile(                                                              \
        "mma.sync.aligned.m16n8k8.row.col.f32.tf32.tf32.f32 "                  \
        "{%0,%1,%2,%3},{%4,%5,%6,%7},{%8,%9},{%0,%1,%2,%3};"                   \
        : "+f"((cc)[0]), "+f"((cc)[1]), "+f"((cc)[2]), "+f"((cc)[3])           \
        : "r"((a)[0]), "r"((a)[1]), "r"((a)[2]), "r"((a)[3]),                  \
          "r"((b)[0]), "r"((b)[1]))

// ---------------- detect dtype + zero degrees (fused) ----------------------
__global__ void zdetect_kernel(const int* __restrict__ e, int n) {
    int i = blockIdx.x * blockDim.x + threadIdx.x;
    if (i < n) g_deg[i] = 0;
    if (blockIdx.x == 0 && threadIdx.x < 32) {
        int l = threadIdx.x;
        int bad = 0;
        for (int j = l; j < 256; j += 32)
            if (e[2 * j + 1] != 0) bad = 1;
        unsigned b = __ballot_sync(0xffffffffu, bad);
        if (l == 0) g_is64 = (b == 0) ? 1 : 0;
    }
}

__device__ __forceinline__ int ldidx(const void* p, long long i, int is64) {
    return is64 ? (int)((const long long*)p)[i] : ((const int*)p)[i];
}

// ---------------- convert indices to int32 + count degrees (fused) ----------
__global__ void convcount_kernel(const void* __restrict__ eidx, long long E) {
    long long t = (long long)blockIdx.x * blockDim.x + threadIdx.x;
    if (t >= E) return;
    int is64 = g_is64;
    int r = ldidx(eidx, t, is64);
    int c = ldidx(eidx, E + t, is64);
    g_row[t] = r;
    g_col[t] = c;
    atomicAdd(&g_deg[c], 1);
}

// ---------------- hierarchical scan (2 stages) ------------------------------
__global__ void scan1_kernel(int n) {
    __shared__ int sh[SCHUNK];
    int t = threadIdx.x;
    int i = blockIdx.x * SCHUNK + t;
    sh[t] = (i < n) ? g_deg[i] : 0;
    __syncthreads();
#pragma unroll
    for (int off = SCHUNK / 2; off; off >>= 1) {
        if (t < off) sh[t] += sh[t + off];
        __syncthreads();
    }
    if (t == 0) g_bsum[blockIdx.x] = sh[0];
}

__global__ void scan3_kernel(int n, int nb) {
    __shared__ int bs[256];
    __shared__ int sh[SCHUNK];
    int t = threadIdx.x;
    if (t < 256) bs[t] = (t < nb) ? g_bsum[t] : 0;
    __syncthreads();
#pragma unroll
    for (int off = 1; off < 256; off <<= 1) {
        int u = (t < 256 && t >= off) ? bs[t - off] : 0;
        __syncthreads();
        if (t < 256) bs[t] += u;
        __syncthreads();
    }
    int boff = (blockIdx.x == 0) ? 0 : bs[blockIdx.x - 1];
    if (blockIdx.x == 0 && t == 0) g_rowptr[n] = bs[nb - 1];

    int i = blockIdx.x * SCHUNK + t;
    int d = (i < n) ? g_deg[i] : 0;
    sh[t] = d;
    __syncthreads();
#pragma unroll
    for (int off = 1; off < SCHUNK; off <<= 1) {
        int u = (t >= off) ? sh[t - off] : 0;
        __syncthreads();
        sh[t] += u;
        __syncthreads();
    }
    if (i < n) {
        int pre = boff + sh[t] - d;
        g_rowptr[i] = pre;
        g_fill[i]   = pre;
        g_dinv[i]   = rsqrtf((float)(d + 1));  // +1 self-loop
    }
}

__global__ void fill_kernel(long long E) {
    long long e = (long long)blockIdx.x * blockDim.x + threadIdx.x;
    if (e >= E) return;
    int c = g_col[e];
    int pos = atomicAdd(&g_fill[c], 1);
    g_src[pos] = g_row[e];
}

// ---------------- W prep: tf32 hi/lo split into mma fragment image ----------
// For element (k, n) of W[128][128]:
//   chunk = k/32, tile = ((k%32)/8)*16 + n/8, reg = (k%8)/4,
//   lane = (n%8)*4 + (k%4)   (matches m16n8k8 B-fragment layout)
__global__ void prep_w_kernel(const float* __restrict__ W) {
    int t = blockIdx.x * blockDim.x + threadIdx.x;
    if (t >= 16384) return;
    int k = t >> 7, n = t & 127;
    float v = W[t];
    float hi = tf32_rna(v);
    float lo = tf32_rna(v - hi);
    int chunk = k >> 5;
    int tile = ((k & 31) >> 3) * 16 + (n >> 3);
    int reg = (k & 7) >> 2;
    int lane = (n & 7) * 4 + (k & 3);
    g_bimg[((chunk * 64 + tile) * 2 + reg) * 32 + lane] = make_float2(hi, lo);
}

// ---------------- mma.sync tf32 GEMM: C[M,128] = A[M,128] @ W[128,128] ------
// 3xTF32 split (hh + hl + lh). Block: 128 rows x 128 cols, 8 warps (2M x 4N),
// warp tile 64x32. K in four 32-wide chunks, fragment-major SMEM staging.
__global__ __launch_bounds__(256, 2)
void tgemm_kernel(const float* __restrict__ A, float* __restrict__ C, int M) {
    extern __shared__ float2 sm2[];
    float2* As = sm2;          // 32 tiles * 4 regs * 33 = 4224 float2
    float2* Bs = sm2 + 4224;   // 64 tiles * 2 regs * 33 = 4224 float2

    int tid = threadIdx.x, lane = tid & 31, wid = tid >> 5;
    int wm = wid >> 2, wn = wid & 3;
    long long row0 = (long long)blockIdx.x * 128;

    float c[4][4][4];
#pragma unroll
    for (int a = 0; a < 4; a++)
#pragma unroll
        for (int b = 0; b < 4; b++)
#pragma unroll
            for (int d = 0; d < 4; d++) c[a][b][d] = 0.f;

    for (int ch = 0; ch < 4; ch++) {
        // stage B fragments (pure copy of prepped image, repad to stride 33)
        const float2* bsrc = g_bimg + ch * 4096;
        for (int i = tid; i < 4096; i += 256) {
            int row = i >> 5, l2 = i & 31;
            Bs[row * 33 + l2] = bsrc[i];
        }
        // stage A chunk: load, tf32 hi/lo split, scatter into fragment slots
        for (int idx = tid; idx < 1024; idx += 256) {
            int r = idx >> 3, q = idx & 7;
            long long gr = row0 + r;
            float4 v = make_float4(0.f, 0.f, 0.f, 0.f);
            if (gr < M) v = __ldg((const float4*)(A + gr * F + ch * 32) + q);
            int ri = r & 15;
            int tile = (r >> 4) * 4 + (q >> 1);
            int regb = (q & 1) * 2 + (ri >> 3);
            int lbase = (ri & 7) * 4;
            float vals[4] = {v.x, v.y, v.z, v.w};
#pragma unroll
            for (int j = 0; j < 4; j++) {
                float hi = tf32_rna(vals[j]);
                float lo = tf32_rna(vals[j] - hi);
                As[(tile * 4 + regb) * 33 + lbase + j] = make_float2(hi, lo);
            }
        }
        __syncthreads();

#pragma unroll
        for (int ks = 0; ks < 4; ks++) {
            unsigned bh[4][2], bl[4][2];
#pragma unroll
            for (int nf = 0; nf < 4; nf++)
#pragma unroll
                for (int rg = 0; rg < 2; rg++) {
                    float2 b = Bs[((ks * 16 + wn * 4 + nf) * 2 + rg) * 33 + lane];
                    bh[nf][rg] = __float_as_uint(b.x);
                    bl[nf][rg] = __float_as_uint(b.y);
                }
#pragma unroll
            for (int mf = 0; mf < 4; mf++) {
                unsigned ah[4], al[4];
                int tile = (wm * 4 + mf) * 4 + ks;
#pragma unroll
                for (int rg = 0; rg < 4; rg++) {
                    float2 a = As[(tile * 4 + rg) * 33 + lane];
                    ah[rg] = __float_as_uint(a.x);
                    al[rg] = __float_as_uint(a.y);
                }
#pragma unroll
                for (int nf = 0; nf < 4; nf++) {
                    MMA_TF32(c[mf][nf], ah, bh[nf]);
                    MMA_TF32(c[mf][nf], ah, bl[nf]);
                    MMA_TF32(c[mf][nf], al, bh[nf]);
                }
            }
        }
        __syncthreads();
    }

    // writeout: c0/c1 -> (row, 2*(lane%4)), c2/c3 -> row+8
#pragma unroll
    for (int mf = 0; mf < 4; mf++) {
        long long r0 = row0 + wm * 64 + mf * 16 + (lane >> 2);
#pragma unroll
        for (int nf = 0; nf < 4; nf++) {
            int col = wn * 32 + nf * 8 + 2 * (lane & 3);
            if (r0 < M)
                *(float2*)(C + r0 * F + col) = make_float2(c[mf][nf][0], c[mf][nf][1]);
            if (r0 + 8 < M)
                *(float2*)(C + (r0 + 8) * F + col) = make_float2(c[mf][nf][2], c[mf][nf][3]);
        }
    }
}

// ---------------- CSR gather aggregation (no atomics), fused epilogue ------
// mode 1: +b1, BN(eval), ReLU.   mode 2: +b2.
__global__ void agg_kernel(int n, int mode,
                           const float* __restrict__ bias,
                           const float* __restrict__ gamma,
                           const float* __restrict__ beta,
                           const float* __restrict__ mean,
                           const float* __restrict__ var) {
    int node = blockIdx.x * (blockDim.x >> 5) + (threadIdx.x >> 5);
    if (node >= n) return;
    int l = threadIdx.x & 31;

    float d = g_dinv[node];
    const float4* hv = (const float4*)g_h;

    float4 acc = hv[(size_t)node * 32 + l];
    float d2 = d * d;
    acc.x *= d2; acc.y *= d2; acc.z *= d2; acc.w *= d2;
    float4 acc2 = make_float4(0.f, 0.f, 0.f, 0.f);

    int s = g_rowptr[node], e2 = g_rowptr[node + 1];
    for (int base = s; base < e2; base += 32) {
        int idx = base + l;
        int r = (idx < e2) ? g_src[idx] : 0;
        float dr = (idx < e2) ? g_dinv[r] : 0.f;
        int m = e2 - base; if (m > 32) m = 32;
        int j = 0;
        for (; j + 2 <= m; j += 2) {
            int r0 = __shfl_sync(0xffffffffu, r, j);
            int r1 = __shfl_sync(0xffffffffu, r, j + 1);
            float n0 = __shfl_sync(0xffffffffu, dr, j) * d;
            float n1 = __shfl_sync(0xffffffffu, dr, j + 1) * d;
            float4 v0 = __ldg(hv + (size_t)r0 * 32 + l);
            float4 v1 = __ldg(hv + (size_t)r1 * 32 + l);
            acc.x += v0.x * n0; acc.y += v0.y * n0;
            acc.z += v0.z * n0; acc.w += v0.w * n0;
            acc2.x += v1.x * n1; acc2.y += v1.y * n1;
            acc2.z += v1.z * n1; acc2.w += v1.w * n1;
        }
        if (j < m) {
            int r0 = __shfl_sync(0xffffffffu, r, j);
            float n0 = __shfl_sync(0xffffffffu, dr, j) * d;
            float4 v0 = __ldg(hv + (size_t)r0 * 32 + l);
            acc.x += v0.x * n0; acc.y += v0.y * n0;
            acc.z += v0.z * n0; acc.w += v0.w * n0;
        }
    }
    acc.x += acc2.x; acc.y += acc2.y; acc.z += acc2.z; acc.w += acc2.w;

    int c0 = 4 * l;
    float out[4] = {acc.x, acc.y, acc.z, acc.w};
    if (mode == 1) {
#pragma unroll
        for (int m = 0; m < 4; m++) {
            int c = c0 + m;
            float v = out[m] + bias[c];
            float sc = gamma[c] * rsqrtf(var[c] + 1e-5f);
            v = (v - mean[c]) * sc + beta[c];
            out[m] = fmaxf(v, 0.f);
        }
    } else {
#pragma unroll
        for (int m = 0; m < 4; m++) out[m] += bias[c0 + m];
    }
    *(float4*)(g_agg + (size_t)node * F + c0) =
        make_float4(out[0], out[1], out[2], out[3]);
}

// ---------------- head weight packing ---------------------------------------
__global__ void pack_heads_kernel(const float* __restrict__ cls_w,
                                  const float* __restrict__ cls_b,
                                  const float* __restrict__ sim_w,
                                  const float* __restrict__ sim_b,
                                  const float* __restrict__ hom_w,
                                  const float* __restrict__ hom_b,
                                  const float* __restrict__ ent_w,
                                  const float* __restrict__ ent_b) {
    int t = blockIdx.x * blockDim.x + threadIdx.x;
    if (t < F * HEADP) {
        int k = t / HEADP, c = t % HEADP;
        float v = 0.f;
        if (c < 64)        v = cls_w[k * 64 + c];
        else if (c < 104)  v = sim_w[k * 40 + (c - 64)];
        else if (c == 104) v = hom_w[k];
        else if (c == 105) v = ent_w[k];
        g_hw[t] = v;
    }
    if (t < HEADP) {
        float v = 0.f;
        if (t < 64)        v = cls_b[t];
        else if (t < 104)  v = sim_b[t - 64];
        else if (t == 104) v = hom_b[0];
        else if (t == 105) v = ent_b[0];
        g_hb[t] = v;
    }
}

// ---------------- head GEMM [M,128]x[128,106] with fused finisher -----------
__global__ void head_kernel(const float* __restrict__ A,
                            float* __restrict__ out, int M) {
    extern __shared__ float sm[];
    float* Ws = sm;                    // F * HEADP
    float* xs = Ws + F * HEADP;        // 8 * 4 * F
    float* sb = xs + 8 * 4 * F;        // HEADP

    int tid = threadIdx.x;
    for (int i = tid; i < F * HEADP; i += blockDim.x) Ws[i] = g_hw[i];
    for (int c = tid; c < HEADP; c += blockDim.x) sb[c] = g_hb[c];
    __syncthreads();

    int wid = tid >> 5, l = tid & 31;
    long long row0 = ((long long)blockIdx.x * 8 + wid) * 4;
    if (row0 >= M) return;

    float* xw = xs + wid * 4 * F;
#pragma unroll
    for (int rr = 0; rr < 4; rr++) {
        long long r = row0 + rr;
        float4 v = make_float4(0.f, 0.f, 0.f, 0.f);
        if (r < M) v = __ldg((const float4*)(A + r * F) + l);
        *(float4*)&xw[rr * F + 4 * l] = v;
    }
    __syncwarp();

    float acc[4][4];
#pragma unroll
    for (int rr = 0; rr < 4; rr++)
#pragma unroll
        for (int m = 0; m < 4; m++) acc[rr][m] = 0.f;

    const float4* WsV = (const float4*)Ws;
    const int ncp4 = HEADP >> 2;  // 27
#pragma unroll
    for (int k = 0; k < F; k += 4) {
        float4 w4[4], xr[4];
#pragma unroll
        for (int kk = 0; kk < 4; kk++)
            w4[kk] = (l < ncp4) ? WsV[(k + kk) * ncp4 + l]
                                : make_float4(0.f, 0.f, 0.f, 0.f);
#pragma unroll
        for (int rr = 0; rr < 4; rr++) xr[rr] = *(const float4*)&xw[rr * F + k];
#pragma unroll
        for (int rr = 0; rr < 4; rr++) {
            const float* xf = (const float*)&xr[rr];
#pragma unroll
            for (int kk = 0; kk < 4; kk++) {
                const float* wf = (const float*)&w4[kk];
                float xv = xf[kk];
                acc[rr][0] += xv * wf[0];
                acc[rr][1] += xv * wf[1];
                acc[rr][2] += xv * wf[2];
                acc[rr][3] += xv * wf[3];
            }
        }
    }

    float* out_main = out;                     // [M,64]
    float* out_sim  = out + (size_t)M * 64;    // [M,40]
    float* out_hom  = out + (size_t)M * 104;   // [M]
    float* out_ent  = out + (size_t)M * 105;   // [M]

    int c0 = 4 * l;
#pragma unroll
    for (int rr = 0; rr < 4; rr++) {
        long long r = row0 + rr;
        if (r >= M) break;
        float v[4];
#pragma unroll
        for (int m = 0; m < 4; m++)
            v[m] = acc[rr][m] + ((l < ncp4) ? sb[c0 + m] : 0.f);

        // log_softmax over cols [0,64) -> lanes 0..15
        float lm = -3.0e38f;
        if (l < 16) {
#pragma unroll
            for (int m = 0; m < 4; m++) lm = fmaxf(lm, v[m]);
        }
#pragma unroll
        for (int o = 16; o; o >>= 1)
            lm = fmaxf(lm, __shfl_xor_sync(0xffffffffu, lm, o));
        float se = 0.f;
        if (l < 16) {
#pragma unroll
            for (int m = 0; m < 4; m++) se += expf(v[m] - lm);
        }
#pragma unroll
        for (int o = 16; o; o >>= 1) se += __shfl_xor_sync(0xffffffffu, se, o);
        float ls = lm + logf(se);
        if (l < 16) {
#pragma unroll
            for (int m = 0; m < 4; m++) out_main[r * 64 + c0 + m] = v[m] - ls;
        }

        // softmax over cols [64,104) -> lanes 16..25
        bool insim = (l >= 16 && l < 26);
        float lm2 = -3.0e38f;
        if (insim) {
#pragma unroll
            for (int m = 0; m < 4; m++) lm2 = fmaxf(lm2, v[m]);
        }
#pragma unroll
        for (int o = 16; o; o >>= 1)
            lm2 = fmaxf(lm2, __shfl_xor_sync(0xffffffffu, lm2, o));
        float e4[4];
        float se2 = 0.f;
        if (insim) {
#pragma unroll
            for (int m = 0; m < 4; m++) { e4[m] = expf(v[m] - lm2); se2 += e4[m]; }
        }
#pragma unroll
        for (int o = 16; o; o >>= 1) se2 += __shfl_xor_sync(0xffffffffu, se2, o);
        if (insim) {
            float inv = 1.f / se2;
#pragma unroll
            for (int m = 0; m < 4; m++)
                out_sim[r * 40 + (c0 - 64) + m] = e4[m] * inv;
        }

        // sigmoids: col 104, 105 -> lane 26
        if (l == 26) {
            out_hom[r] = 1.f / (1.f + expf(-v[0]));
            out_ent[r] = 1.f / (1.f + expf(-v[1]));
        }
    }
}

// ---------------- launch ------------------------------------------------------
extern "C" void kernel_launch(void* const* d_in, const int* in_sizes, int n_in,
                              void* d_out, int out_size) {
    const float* x     = (const float*)d_in[0];
    const void*  eidx  = d_in[1];
    const float* w1    = (const float*)d_in[2];
    const float* b1    = (const float*)d_in[3];
    const float* w2    = (const float*)d_in[4];
    const float* b2    = (const float*)d_in[5];
    const float* gamma = (const float*)d_in[6];
    const float* beta  = (const float*)d_in[7];
    const float* mean  = (const float*)d_in[8];
    const float* var   = (const float*)d_in[9];
    const float* cls_w = (const float*)d_in[10];
    const float* cls_b = (const float*)d_in[11];
    const float* sim_w = (const float*)d_in[12];
    const float* sim_b = (const float*)d_in[13];
    const float* hom_w = (const float*)d_in[14];
    const float* hom_b = (const float*)d_in[15];
    const float* ent_w = (const float*)d_in[16];
    const float* ent_b = (const float*)d_in[17];

    int N = in_sizes[0] / F;
    long long E = (long long)in_sizes[1] / 2;
    float* out = (float*)d_out;

    float *p_h = nullptr, *p_agg = nullptr;
    cudaGetSymbolAddress((void**)&p_h, g_h);
    cudaGetSymbolAddress((void**)&p_agg, g_agg);

    size_t smemT = 8448 * sizeof(float2);                 // 67.6 KB
    size_t smemH = (size_t)(F * HEADP + 8 * 4 * F + HEADP) * sizeof(float);
    cudaFuncSetAttribute(tgemm_kernel, cudaFuncAttributeMaxDynamicSharedMemorySize,
                         (int)smemT);
    cudaFuncSetAttribute(head_kernel, cudaFuncAttributeMaxDynamicSharedMemorySize,
                         96 * 1024);

    int tb = 256;
    int nscan = (N + SCHUNK - 1) / SCHUNK;
    int tgG = (N + 127) / 128;

    // preprocessing
    zdetect_kernel<<<(N + tb - 1) / tb, tb>>>((const int*)eidx, N);
    convcount_kernel<<<(unsigned)((E + tb - 1) / tb), tb>>>(eidx, E);
    scan1_kernel<<<nscan, SCHUNK>>>(N);
    scan3_kernel<<<nscan, SCHUNK>>>(N, nscan);
    fill_kernel<<<(unsigned)((E + tb - 1) / tb), tb>>>(E);

    // layer 1
    prep_w_kernel<<<64, 256>>>(w1);
    tgemm_kernel<<<tgG, tb, smemT>>>(x, p_h, N);
    agg_kernel<<<(N + 7) / 8, tb>>>(N, 1, b1, gamma, beta, mean, var);

    // layer 2
    prep_w_kernel<<<64, 256>>>(w2);
    tgemm_kernel<<<tgG, tb, smemT>>>(p_agg, p_h, N);
    agg_kernel<<<(N + 7) / 8, tb>>>(N, 2, b2, nullptr, nullptr, nullptr, nullptr);

    // heads (fused finisher)
    pack_heads_kernel<<<(F * HEADP + tb - 1) / tb, tb>>>(cls_w, cls_b, sim_w, sim_b,
                                                         hom_w, hom_b, ent_w, ent_b);
    head_kernel<<<(N + 31) / 32, tb, smemH>>>(p_agg, out, N);
}